// round 12
// baseline (speedup 1.0000x reference)
#include <cuda_runtime.h>

#define NB   4
#define NN   50000
#define FIN  32
#define H2   30
#define BN   (NB*NN)       // 200000 node-batch rows
#define BD   128           // edge-kernel block size
#define PB   256           // proj/out block size
#define IG   1024          // init grid

typedef unsigned long long ull;

// Static scratch (no allocations allowed).
__device__ __align__(128) float g_YA[(size_t)BN*32];   // x @ W1[0:32]
__device__ __align__(128) float g_YB[(size_t)BN*32];   // x @ W1[32:64] + b1
__device__ __align__(128) float g_SC[(size_t)BN*32];   // padded 30->32 accumulator
__device__ double g_sum, g_sumsq;
__device__ float  g_mean, g_istd;
__device__ int    g_is64;
__device__ unsigned g_ticket;

union F4U2 { float4 f4; ull u[2]; float f[4]; };
union F2U1 { float2 f2; ull u; float f[2]; };

__device__ __forceinline__ float sigmoidf(float x){          // final layer
    return __fdividef(1.0f, 1.0f + __expf(-x));
}
__device__ __forceinline__ float sigm_fast(float x){         // hidden layers
    float t;
    asm("tanh.approx.f32 %0, %1;" : "=f"(t) : "f"(x * 0.5f));
    return fmaf(t, 0.5f, 0.5f);
}
__device__ __forceinline__ ull pack2(float lo, float hi){
    ull r; asm("mov.b64 %0, {%1,%2};" : "=l"(r) : "f"(lo), "f"(hi)); return r;
}
#define FMA2(acc, a, b) asm("fma.rn.f32x2 %0, %1, %2, %0;" : "+l"(acc) : "l"(a), "l"(b))
#define ADD2(d, a, b)   asm("add.rn.f32x2 %0, %1, %2;"     : "=l"(d)  : "l"(a), "l"(b))

__device__ __forceinline__ void red_add_v4(float* p, float a, float b, float c, float d){
    asm volatile("red.global.add.v4.f32 [%0], {%1,%2,%3,%4};"
                 :: "l"(p), "f"(a), "f"(b), "f"(c), "f"(d) : "memory");
}
__device__ __forceinline__ void red_add_v2(float* p, float a, float b){
    asm volatile("red.global.add.v2.f32 [%0], {%1,%2};"
                 :: "l"(p), "f"(a), "f"(b) : "memory");
}

// ---------------- K0: zero SC + edge_attr stats + probe + finalize (fused) ----------------
__global__ void k_init(const int* __restrict__ ei32, const float* __restrict__ ea, int E){
    size_t n4 = (size_t)BN*32/4;
    float4 z = make_float4(0.f,0.f,0.f,0.f);
    float4* p = (float4*)g_SC;
    for (size_t i = (size_t)blockIdx.x*blockDim.x + threadIdx.x; i < n4;
         i += (size_t)gridDim.x*blockDim.x) p[i] = z;

    if (blockIdx.x==0 && threadIdx.x==0){
        int all_hi_zero = 1;
        for (int k = 1; k < 512; k += 2) all_hi_zero &= (ei32[k] == 0);
        g_is64 = all_hi_zero;
    }

    float s = 0.f, s2 = 0.f;
    for (int i = blockIdx.x*blockDim.x + threadIdx.x; i < E; i += gridDim.x*blockDim.x){
        float v = ea[i]; s += v; s2 = fmaf(v, v, s2);
    }
    #pragma unroll
    for (int o = 16; o; o >>= 1){
        s  += __shfl_down_sync(0xffffffffu, s,  o);
        s2 += __shfl_down_sync(0xffffffffu, s2, o);
    }
    __shared__ float ws[32], ws2[32];
    __shared__ int last;
    int lane = threadIdx.x & 31, w = threadIdx.x >> 5;
    if (lane == 0){ ws[w] = s; ws2[w] = s2; }
    __syncthreads();
    if (w == 0){
        int nw = blockDim.x >> 5;
        s  = (lane < nw) ? ws[lane]  : 0.f;
        s2 = (lane < nw) ? ws2[lane] : 0.f;
        #pragma unroll
        for (int o = 16; o; o >>= 1){
            s  += __shfl_down_sync(0xffffffffu, s,  o);
            s2 += __shfl_down_sync(0xffffffffu, s2, o);
        }
        if (lane == 0){ atomicAdd(&g_sum, (double)s); atomicAdd(&g_sumsq, (double)s2); }
    }
    if (threadIdx.x == 0){
        __threadfence();
        unsigned t = atomicAdd(&g_ticket, 1u);
        last = (t == (unsigned)(gridDim.x - 1));
    }
    __syncthreads();
    if (last && threadIdx.x == 0){
        double S = g_sum, S2 = g_sumsq;
        double mean = S / (double)E;
        double var  = (S2 - S*S/(double)E) / (double)(E - 1);
        g_mean = (float)mean;
        g_istd = (float)(1.0 / sqrt(var));
        g_ticket = 0u;
        g_sum = 0.0; g_sumsq = 0.0;
    }
}

// ---------------- KB: per-node projections, split halves, smem-staged I/O ----------------
__global__ __launch_bounds__(PB) void k_proj(
    const float* __restrict__ x, const float* __restrict__ W1,
    const float* __restrict__ b1)
{
    __shared__ float4 st[PB*9];
    __shared__ __align__(16) float sW[32*32];
    __shared__ __align__(16) float sb[32];
    int half = blockIdx.y;
    int tid = threadIdx.x;
    for (int k = tid; k < 32*32; k += PB) sW[k] = W1[half*32*32 + k];
    if (tid < 32) sb[tid] = half ? b1[tid] : 0.f;

    int base = blockIdx.x*PB;
    const float4* x4 = (const float4*)x;
    #pragma unroll
    for (int k = tid; k < PB*8; k += PB){
        int row = k >> 3, q = k & 7;
        int gr = base + row;
        if (gr < BN) st[row*9 + q] = x4[(size_t)gr*8 + q];
    }
    __syncthreads();

    F4U2 xr[8];
    #pragma unroll
    for (int q = 0; q < 8; q++) xr[q].f4 = st[tid*9 + q];

    __align__(16) ull acc[16];
    const float4* sb4 = (const float4*)sb;
    #pragma unroll
    for (int q = 0; q < 8; q++){
        F4U2 b; b.f4 = sb4[q];
        acc[2*q] = b.u[0]; acc[2*q+1] = b.u[1];
    }
    #pragma unroll
    for (int i = 0; i < 32; i++){
        float v = xr[i >> 2].f[i & 3];
        ull vv = pack2(v, v);
        const float4* wr = (const float4*)(sW + i*32);
        #pragma unroll
        for (int q = 0; q < 8; q++){
            F4U2 w; w.f4 = wr[q];
            FMA2(acc[2*q],   vv, w.u[0]);
            FMA2(acc[2*q+1], vv, w.u[1]);
        }
    }
    __syncthreads();
    const float4* aa = (const float4*)acc;
    #pragma unroll
    for (int q = 0; q < 8; q++) st[tid*9 + q] = aa[q];
    __syncthreads();
    float4* y4 = (float4*)(half ? g_YB : g_YA);
    #pragma unroll
    for (int k = tid; k < PB*8; k += PB){
        int row = k >> 3, q = k & 7;
        int gr = base + row;
        if (gr < BN) y4[(size_t)gr*8 + q] = st[row*9 + q];
    }
}

// ---------------- KD: edge MLP, fused gather-add, in-place sigm, high occupancy ----------------
__global__ __launch_bounds__(BD, 9) void k_edge(
    const int* __restrict__ ei32, const float* __restrict__ eattr,
    const float* __restrict__ W1, const float* __restrict__ W2,
    const float* __restrict__ b2, int E)
{
    __shared__ float4 sS[BD*9];                 // staged YA[src]+YB[tgt], stride 9
    __shared__ __align__(16) float sW2[32*32];  // 32 rows, stride 32, cols 0..29 used
    __shared__ __align__(16) float sw1c[32];
    __shared__ __align__(16) float sb2[32];

    int tid = threadIdx.x;
    int lane = tid & 31, w = tid >> 5;

    for (int k = tid; k < 32*32; k += BD){
        int i = k >> 5, j = k & 31;
        sW2[k] = (j < H2) ? W2[i*H2 + j] : 0.f;
    }
    if (tid < 32){
        sw1c[tid] = W1[64*32 + tid];
        sb2[tid]  = (tid < H2) ? b2[tid] : 0.f;
    }
    __syncthreads();                          // ONLY block barrier (weights visible)

    long long item  = (long long)blockIdx.x*BD + tid;
    bool active = item < 4LL*E;
    int e = active ? (int)(item >> 2) : 0;
    int b = (int)(item & 3);
    int is64 = g_is64;
    int src, tgt;
    if (is64){ src = ei32[2*(size_t)e]; tgt = ei32[2*((size_t)E + e)]; }
    else     { src = ei32[e];           tgt = ei32[E + e]; }
    float ea = active ? (eattr[e] - g_mean) * g_istd : 0.f;
    int ia = b*NN + src;                      // subtract side
    int ib = b*NN + tgt;                      // add side

    // Warp-local coalesced gather with fused add: 8 lanes service one item row.
    const float4* ya4 = (const float4*)g_YA;
    const float4* yb4 = (const float4*)g_YB;
    int rowbase = w*32;
    int q = lane & 7;
    #pragma unroll
    for (int it = 0; it < 8; it++){
        int iw = 4*it + (lane >> 3);          // item-in-warp 0..31
        int iaW = __shfl_sync(0xffffffffu, ia, iw);
        int ibW = __shfl_sync(0xffffffffu, ib, iw);
        int R = rowbase + iw;
        float4 va = ya4[(size_t)iaW*8 + q];
        float4 vb = yb4[(size_t)ibW*8 + q];
        float4 vs;
        vs.x = va.x + vb.x; vs.y = va.y + vb.y;
        vs.z = va.z + vb.z; vs.w = va.w + vb.w;
        sS[R*9 + q] = vs;
    }
    __syncwarp();                             // warp-local staging only

    // Interleaved layer1 + layer2; h2 lives only inside acc (in-place sigm).
    __align__(16) ull acc[15];
    const float4* sb24 = (const float4*)sb2;
    #pragma unroll
    for (int p = 0; p < 7; p++){
        F4U2 bb; bb.f4 = sb24[p];
        acc[2*p] = bb.u[0]; acc[2*p+1] = bb.u[1];
    }
    { F2U1 bt; bt.f2 = *(const float2*)(sb2 + 28); acc[14] = bt.u; }

    ull eaea = pack2(ea, ea);
    const float4* w1c4 = (const float4*)sw1c;
    #pragma unroll
    for (int p = 0; p < 8; p++){
        F4U2 a; a.f4 = sS[tid*9 + p];
        F4U2 wv; wv.f4 = w1c4[p];
        ull s0 = a.u[0], s1 = a.u[1];
        FMA2(s0, eaea, wv.u[0]);
        FMA2(s1, eaea, wv.u[1]);
        F4U2 r; r.u[0] = s0; r.u[1] = s1;
        #pragma unroll
        for (int c = 0; c < 4; c++){
            float hv = sigm_fast(r.f[c]);
            ull hh = pack2(hv, hv);
            const float4* wr = (const float4*)(sW2 + (4*p + c)*32);
            #pragma unroll
            for (int m = 0; m < 7; m++){
                F4U2 w2v; w2v.f4 = wr[m];
                FMA2(acc[2*m],   hh, w2v.u[0]);
                FMA2(acc[2*m+1], hh, w2v.u[1]);
            }
            F2U1 wt; wt.f2 = *(const float2*)(sW2 + (4*p + c)*32 + 28);
            FMA2(acc[14], hh, wt.u);
        }
    }
    // In-place sigmoid: overwrite acc with activated values.
    #pragma unroll
    for (int p = 0; p < 15; p++){
        F2U1 r; r.u = acc[p];
        r.f[0] = sigm_fast(r.f[0]);
        r.f[1] = sigm_fast(r.f[1]);
        acc[p] = r.u;
    }

    if (active){
        float* pt = g_SC + (size_t)ib*32;
        float* ps = g_SC + (size_t)ia*32;
        const float* hv = (const float*)acc;
        #pragma unroll
        for (int p = 0; p < 7; p++){
            red_add_v4(pt + 4*p,  hv[4*p],  hv[4*p+1],  hv[4*p+2],  hv[4*p+3]);
            red_add_v4(ps + 4*p, -hv[4*p], -hv[4*p+1], -hv[4*p+2], -hv[4*p+3]);
        }
        red_add_v2(pt + 28,  hv[28],  hv[29]);
        red_add_v2(ps + 28, -hv[28], -hv[29]);
    }
}

// ---------------- KE: out = sigmoid(SC @ W3 + b3), split 16-col halves, staged I/O ----------------
__global__ __launch_bounds__(PB) void k_out(
    float* __restrict__ out, const float* __restrict__ W3,
    const float* __restrict__ b3)
{
    __shared__ float4 st[PB*9];
    __shared__ __align__(16) float sW[30*16];
    __shared__ __align__(16) float sb[16];
    int half = blockIdx.y;
    int tid = threadIdx.x;
    for (int k = tid; k < 30*16; k += PB){
        int r = k >> 4, c = k & 15;
        sW[k] = W3[r*32 + half*16 + c];
    }
    if (tid < 16) sb[tid] = b3[half*16 + tid];

    int base = blockIdx.x*PB;
    const float4* sc4 = (const float4*)g_SC;
    #pragma unroll
    for (int k = tid; k < PB*8; k += PB){
        int row = k >> 3, q = k & 7;
        int gr = base + row;
        if (gr < BN) st[row*9 + q] = sc4[(size_t)gr*8 + q];
    }
    __syncthreads();

    F4U2 sr[8];
    #pragma unroll
    for (int q = 0; q < 8; q++) sr[q].f4 = st[tid*9 + q];

    __align__(16) ull acc[8];
    const float4* sb4 = (const float4*)sb;
    #pragma unroll
    for (int q = 0; q < 4; q++){
        F4U2 bb; bb.f4 = sb4[q];
        acc[2*q] = bb.u[0]; acc[2*q+1] = bb.u[1];
    }
    #pragma unroll
    for (int k = 0; k < 30; k++){
        float sv = sr[k >> 2].f[k & 3];
        ull vv = pack2(sv, sv);
        const float4* wr = (const float4*)(sW + k*16);
        #pragma unroll
        for (int q = 0; q < 4; q++){
            F4U2 w; w.f4 = wr[q];
            FMA2(acc[2*q],   vv, w.u[0]);
            FMA2(acc[2*q+1], vv, w.u[1]);
        }
    }
    __align__(16) float res[16];
    #pragma unroll
    for (int q = 0; q < 4; q++){
        F4U2 r; r.u[0] = acc[2*q]; r.u[1] = acc[2*q+1];
        res[4*q+0] = sigmoidf(r.f[0]);
        res[4*q+1] = sigmoidf(r.f[1]);
        res[4*q+2] = sigmoidf(r.f[2]);
        res[4*q+3] = sigmoidf(r.f[3]);
    }

    __syncthreads();
    float4* st5 = (float4*)st;
    const float4* rr = (const float4*)res;
    #pragma unroll
    for (int q = 0; q < 4; q++) st5[tid*5 + q] = rr[q];
    __syncthreads();
    float4* o4 = (float4*)out;
    #pragma unroll
    for (int k = tid; k < PB*4; k += PB){
        int row = k >> 2, q = k & 3;
        int gr = base + row;
        if (gr < BN) o4[(size_t)gr*8 + half*4 + q] = st5[row*5 + q];
    }
}

extern "C" void kernel_launch(void* const* d_in, const int* in_sizes, int n_in,
                              void* d_out, int out_size){
    const float* x     = (const float*)d_in[0];
    const int*   ei32  = (const int*)d_in[1];
    const float* eattr = (const float*)d_in[2];
    const float* W1    = (const float*)d_in[3];
    const float* b1    = (const float*)d_in[4];
    const float* W2    = (const float*)d_in[5];
    const float* b2    = (const float*)d_in[6];
    const float* W3    = (const float*)d_in[7];
    const float* b3    = (const float*)d_in[8];
    int E = in_sizes[1] / 2;

    k_init<<<IG, 256>>>(ei32, eattr, E);
    dim3 pg((BN + PB - 1)/PB, 2);
    k_proj<<<pg, PB>>>(x, W1, b1);
    long long items = 4LL * E;
    int blocks = (int)((items + BD - 1) / BD);
    k_edge<<<blocks, BD>>>(ei32, eattr, W1, W2, b2, E);
    k_out<<<pg, PB>>>((float*)d_out, W3, b3);
}

// round 13
// speedup vs baseline: 1.1750x; 1.1750x over previous
#include <cuda_runtime.h>

#define NB   4
#define NN   50000
#define FIN  32
#define H2   30
#define BN   (NB*NN)       // 200000 node-batch rows
#define BD   128           // edge-kernel block size
#define PB   256           // proj/out block size
#define IG   1024          // init grid

typedef unsigned long long ull;

// Static scratch (no allocations allowed).
__device__ __align__(128) float g_YA[(size_t)BN*32];   // x @ W1[0:32]
__device__ __align__(128) float g_YB[(size_t)BN*32];   // x @ W1[32:64] + b1
__device__ __align__(128) float g_SC[(size_t)BN*32];   // padded 30->32 accumulator
__device__ double g_sum, g_sumsq;
__device__ float  g_mean, g_istd;
__device__ int    g_is64;
__device__ unsigned g_ticket;

union F4U2 { float4 f4; ull u[2]; float f[4]; };
union F2U1 { float2 f2; ull u; float f[2]; };

__device__ __forceinline__ float sigmoidf(float x){          // final layer
    return __fdividef(1.0f, 1.0f + __expf(-x));
}
__device__ __forceinline__ float sigm_fast(float x){         // hidden layers
    float t;
    asm("tanh.approx.f32 %0, %1;" : "=f"(t) : "f"(x * 0.5f));
    return fmaf(t, 0.5f, 0.5f);
}
__device__ __forceinline__ ull pack2(float lo, float hi){
    ull r; asm("mov.b64 %0, {%1,%2};" : "=l"(r) : "f"(lo), "f"(hi)); return r;
}
#define FMA2(acc, a, b) asm("fma.rn.f32x2 %0, %1, %2, %0;" : "+l"(acc) : "l"(a), "l"(b))
#define ADD2(d, a, b)   asm("add.rn.f32x2 %0, %1, %2;"     : "=l"(d)  : "l"(a), "l"(b))

__device__ __forceinline__ void red_add_v4(float* p, float a, float b, float c, float d){
    asm volatile("red.global.add.v4.f32 [%0], {%1,%2,%3,%4};"
                 :: "l"(p), "f"(a), "f"(b), "f"(c), "f"(d) : "memory");
}

// ---------------- K0: zero SC + edge_attr stats + probe + finalize (fused) ----------------
__global__ void k_init(const int* __restrict__ ei32, const float* __restrict__ ea, int E){
    size_t n4 = (size_t)BN*32/4;
    float4 z = make_float4(0.f,0.f,0.f,0.f);
    float4* p = (float4*)g_SC;
    for (size_t i = (size_t)blockIdx.x*blockDim.x + threadIdx.x; i < n4;
         i += (size_t)gridDim.x*blockDim.x) p[i] = z;

    if (blockIdx.x==0 && threadIdx.x==0){
        int all_hi_zero = 1;
        for (int k = 1; k < 512; k += 2) all_hi_zero &= (ei32[k] == 0);
        g_is64 = all_hi_zero;
    }

    float s = 0.f, s2 = 0.f;
    for (int i = blockIdx.x*blockDim.x + threadIdx.x; i < E; i += gridDim.x*blockDim.x){
        float v = ea[i]; s += v; s2 = fmaf(v, v, s2);
    }
    #pragma unroll
    for (int o = 16; o; o >>= 1){
        s  += __shfl_down_sync(0xffffffffu, s,  o);
        s2 += __shfl_down_sync(0xffffffffu, s2, o);
    }
    __shared__ float ws[32], ws2[32];
    __shared__ int last;
    int lane = threadIdx.x & 31, w = threadIdx.x >> 5;
    if (lane == 0){ ws[w] = s; ws2[w] = s2; }
    __syncthreads();
    if (w == 0){
        int nw = blockDim.x >> 5;
        s  = (lane < nw) ? ws[lane]  : 0.f;
        s2 = (lane < nw) ? ws2[lane] : 0.f;
        #pragma unroll
        for (int o = 16; o; o >>= 1){
            s  += __shfl_down_sync(0xffffffffu, s,  o);
            s2 += __shfl_down_sync(0xffffffffu, s2, o);
        }
        if (lane == 0){ atomicAdd(&g_sum, (double)s); atomicAdd(&g_sumsq, (double)s2); }
    }
    if (threadIdx.x == 0){
        __threadfence();
        unsigned t = atomicAdd(&g_ticket, 1u);
        last = (t == (unsigned)(gridDim.x - 1));
    }
    __syncthreads();
    if (last && threadIdx.x == 0){
        double S = g_sum, S2 = g_sumsq;
        double mean = S / (double)E;
        double var  = (S2 - S*S/(double)E) / (double)(E - 1);
        g_mean = (float)mean;
        g_istd = (float)(1.0 / sqrt(var));
        g_ticket = 0u;
        g_sum = 0.0; g_sumsq = 0.0;
    }
}

// ---------------- KB: per-node projections, split halves, smem-staged I/O ----------------
__global__ __launch_bounds__(PB) void k_proj(
    const float* __restrict__ x, const float* __restrict__ W1,
    const float* __restrict__ b1)
{
    __shared__ float4 st[PB*9];
    __shared__ __align__(16) float sW[32*32];
    __shared__ __align__(16) float sb[32];
    int half = blockIdx.y;
    int tid = threadIdx.x;
    for (int k = tid; k < 32*32; k += PB) sW[k] = W1[half*32*32 + k];
    if (tid < 32) sb[tid] = half ? b1[tid] : 0.f;

    int base = blockIdx.x*PB;
    const float4* x4 = (const float4*)x;
    #pragma unroll
    for (int k = tid; k < PB*8; k += PB){
        int row = k >> 3, q = k & 7;
        int gr = base + row;
        if (gr < BN) st[row*9 + q] = x4[(size_t)gr*8 + q];
    }
    __syncthreads();

    F4U2 xr[8];
    #pragma unroll
    for (int q = 0; q < 8; q++) xr[q].f4 = st[tid*9 + q];

    __align__(16) ull acc[16];
    const float4* sb4 = (const float4*)sb;
    #pragma unroll
    for (int q = 0; q < 8; q++){
        F4U2 b; b.f4 = sb4[q];
        acc[2*q] = b.u[0]; acc[2*q+1] = b.u[1];
    }
    #pragma unroll
    for (int i = 0; i < 32; i++){
        float v = xr[i >> 2].f[i & 3];
        ull vv = pack2(v, v);
        const float4* wr = (const float4*)(sW + i*32);
        #pragma unroll
        for (int q = 0; q < 8; q++){
            F4U2 w; w.f4 = wr[q];
            FMA2(acc[2*q],   vv, w.u[0]);
            FMA2(acc[2*q+1], vv, w.u[1]);
        }
    }
    __syncthreads();
    const float4* aa = (const float4*)acc;
    #pragma unroll
    for (int q = 0; q < 8; q++) st[tid*9 + q] = aa[q];
    __syncthreads();
    float4* y4 = (float4*)(half ? g_YB : g_YA);
    #pragma unroll
    for (int k = tid; k < PB*8; k += PB){
        int row = k >> 3, q = k & 7;
        int gr = base + row;
        if (gr < BN) y4[(size_t)gr*8 + q] = st[row*9 + q];
    }
}

// ---------------- KD: edge MLP, warp-local gather AND warp-local scatter ----------------
__global__ __launch_bounds__(BD) void k_edge(
    const int* __restrict__ ei32, const float* __restrict__ eattr,
    const float* __restrict__ W1, const float* __restrict__ W2,
    const float* __restrict__ b2, int E)
{
    __shared__ float4 sS[BD*9];                 // staged rows (36 floats/row)
    __shared__ __align__(16) float sW2[32*32];  // 32 rows, stride 32, cols 0..29 used
    __shared__ __align__(16) float sw1c[32];
    __shared__ __align__(16) float sb2[32];

    int tid = threadIdx.x;
    int lane = tid & 31, w = tid >> 5;

    for (int k = tid; k < 32*32; k += BD){
        int i = k >> 5, j = k & 31;
        sW2[k] = (j < H2) ? W2[i*H2 + j] : 0.f;
    }
    if (tid < 32){
        sw1c[tid] = W1[64*32 + tid];
        sb2[tid]  = (tid < H2) ? b2[tid] : 0.f;
    }
    __syncthreads();                          // ONLY block barrier (weights visible)

    long long item  = (long long)blockIdx.x*BD + tid;
    bool active = item < 4LL*E;
    int e = active ? (int)(item >> 2) : 0;
    int b = (int)(item & 3);
    int is64 = g_is64;
    int src, tgt;
    if (is64){ src = ei32[2*(size_t)e]; tgt = ei32[2*((size_t)E + e)]; }
    else     { src = ei32[e];           tgt = ei32[E + e]; }
    float ea = active ? (eattr[e] - g_mean) * g_istd : 0.f;
    int ia = b*NN + src;                      // subtract side
    int ib = b*NN + tgt;                      // add side

    // Warp-local coalesced gather with fused add: 8 lanes service one item row.
    const float4* ya4 = (const float4*)g_YA;
    const float4* yb4 = (const float4*)g_YB;
    int rowbase = w*32;
    int q = lane & 7;
    int grp = lane >> 3;                      // 0..3
    #pragma unroll
    for (int it = 0; it < 8; it++){
        int iw = 4*it + grp;                  // item-in-warp 0..31
        int iaW = __shfl_sync(0xffffffffu, ia, iw);
        int ibW = __shfl_sync(0xffffffffu, ib, iw);
        int R = rowbase + iw;
        float4 va = ya4[(size_t)iaW*8 + q];
        float4 vb = yb4[(size_t)ibW*8 + q];
        float4 vs;
        vs.x = va.x + vb.x; vs.y = va.y + vb.y;
        vs.z = va.z + vb.z; vs.w = va.w + vb.w;
        sS[R*9 + q] = vs;
    }
    __syncwarp();                             // warp-local staging only

    // Interleaved layer1 + layer2; h2 lives only inside acc (in-place sigm).
    __align__(16) ull acc[15];
    const float4* sb24 = (const float4*)sb2;
    #pragma unroll
    for (int p = 0; p < 7; p++){
        F4U2 bb; bb.f4 = sb24[p];
        acc[2*p] = bb.u[0]; acc[2*p+1] = bb.u[1];
    }
    { F2U1 bt; bt.f2 = *(const float2*)(sb2 + 28); acc[14] = bt.u; }

    ull eaea = pack2(ea, ea);
    const float4* w1c4 = (const float4*)sw1c;
    #pragma unroll
    for (int p = 0; p < 8; p++){
        F4U2 a; a.f4 = sS[tid*9 + p];
        F4U2 wv; wv.f4 = w1c4[p];
        ull s0 = a.u[0], s1 = a.u[1];
        FMA2(s0, eaea, wv.u[0]);
        FMA2(s1, eaea, wv.u[1]);
        F4U2 r; r.u[0] = s0; r.u[1] = s1;
        #pragma unroll
        for (int c = 0; c < 4; c++){
            float hv = sigm_fast(r.f[c]);
            ull hh = pack2(hv, hv);
            const float4* wr = (const float4*)(sW2 + (4*p + c)*32);
            #pragma unroll
            for (int m = 0; m < 7; m++){
                F4U2 w2v; w2v.f4 = wr[m];
                FMA2(acc[2*m],   hh, w2v.u[0]);
                FMA2(acc[2*m+1], hh, w2v.u[1]);
            }
            F2U1 wt; wt.f2 = *(const float2*)(sW2 + (4*p + c)*32 + 28);
            FMA2(acc[14], hh, wt.u);
        }
    }

    // In-place sigmoid, masked by activity, staged back into OWN sS row
    // (36-float stride; cols 30,31 zero-padded so the scatter is uniform red.v4).
    float msk = active ? 1.f : 0.f;
    float* mr = (float*)sS + tid*36;
    const float* av = (const float*)acc;
    #pragma unroll
    for (int p = 0; p < 7; p++){
        float4 v;
        v.x = sigm_fast(av[4*p+0]) * msk;
        v.y = sigm_fast(av[4*p+1]) * msk;
        v.z = sigm_fast(av[4*p+2]) * msk;
        v.w = sigm_fast(av[4*p+3]) * msk;
        *(float4*)(mr + 4*p) = v;
    }
    {
        float4 v;
        v.x = sigm_fast(av[28]) * msk;
        v.y = sigm_fast(av[29]) * msk;
        v.z = 0.f; v.w = 0.f;
        *(float4*)(mr + 28) = v;
    }
    __syncwarp();

    // Warp-local coalesced scatter: 8 lanes cover one item's 32-float row;
    // each red.v4 instruction touches 4 full 128B lines (vs 32 scattered).
    float* sH = (float*)sS;
    #pragma unroll
    for (int it = 0; it < 8; it++){
        int iw = 4*it + grp;
        int iaW = __shfl_sync(0xffffffffu, ia, iw);
        int ibW = __shfl_sync(0xffffffffu, ib, iw);
        int R = rowbase + iw;
        float4 v = *(const float4*)(sH + R*36 + 4*q);
        red_add_v4(g_SC + (size_t)ibW*32 + 4*q,  v.x,  v.y,  v.z,  v.w);
        red_add_v4(g_SC + (size_t)iaW*32 + 4*q, -v.x, -v.y, -v.z, -v.w);
    }
}

// ---------------- KE: out = sigmoid(SC @ W3 + b3), split 16-col halves, staged I/O ----------------
__global__ __launch_bounds__(PB) void k_out(
    float* __restrict__ out, const float* __restrict__ W3,
    const float* __restrict__ b3)
{
    __shared__ float4 st[PB*9];
    __shared__ __align__(16) float sW[30*16];
    __shared__ __align__(16) float sb[16];
    int half = blockIdx.y;
    int tid = threadIdx.x;
    for (int k = tid; k < 30*16; k += PB){
        int r = k >> 4, c = k & 15;
        sW[k] = W3[r*32 + half*16 + c];
    }
    if (tid < 16) sb[tid] = b3[half*16 + tid];

    int base = blockIdx.x*PB;
    const float4* sc4 = (const float4*)g_SC;
    #pragma unroll
    for (int k = tid; k < PB*8; k += PB){
        int row = k >> 3, q = k & 7;
        int gr = base + row;
        if (gr < BN) st[row*9 + q] = sc4[(size_t)gr*8 + q];
    }
    __syncthreads();

    F4U2 sr[8];
    #pragma unroll
    for (int q = 0; q < 8; q++) sr[q].f4 = st[tid*9 + q];

    __align__(16) ull acc[8];
    const float4* sb4 = (const float4*)sb;
    #pragma unroll
    for (int q = 0; q < 4; q++){
        F4U2 bb; bb.f4 = sb4[q];
        acc[2*q] = bb.u[0]; acc[2*q+1] = bb.u[1];
    }
    #pragma unroll
    for (int k = 0; k < 30; k++){
        float sv = sr[k >> 2].f[k & 3];
        ull vv = pack2(sv, sv);
        const float4* wr = (const float4*)(sW + k*16);
        #pragma unroll
        for (int q = 0; q < 4; q++){
            F4U2 w; w.f4 = wr[q];
            FMA2(acc[2*q],   vv, w.u[0]);
            FMA2(acc[2*q+1], vv, w.u[1]);
        }
    }
    __align__(16) float res[16];
    #pragma unroll
    for (int q = 0; q < 4; q++){
        F4U2 r; r.u[0] = acc[2*q]; r.u[1] = acc[2*q+1];
        res[4*q+0] = sigmoidf(r.f[0]);
        res[4*q+1] = sigmoidf(r.f[1]);
        res[4*q+2] = sigmoidf(r.f[2]);
        res[4*q+3] = sigmoidf(r.f[3]);
    }

    __syncthreads();
    float4* st5 = (float4*)st;
    const float4* rr = (const float4*)res;
    #pragma unroll
    for (int q = 0; q < 4; q++) st5[tid*5 + q] = rr[q];
    __syncthreads();
    float4* o4 = (float4*)out;
    #pragma unroll
    for (int k = tid; k < PB*4; k += PB){
        int row = k >> 2, q = k & 3;
        int gr = base + row;
        if (gr < BN) o4[(size_t)gr*8 + half*4 + q] = st5[row*5 + q];
    }
}

extern "C" void kernel_launch(void* const* d_in, const int* in_sizes, int n_in,
                              void* d_out, int out_size){
    const float* x     = (const float*)d_in[0];
    const int*   ei32  = (const int*)d_in[1];
    const float* eattr = (const float*)d_in[2];
    const float* W1    = (const float*)d_in[3];
    const float* b1    = (const float*)d_in[4];
    const float* W2    = (const float*)d_in[5];
    const float* b2    = (const float*)d_in[6];
    const float* W3    = (const float*)d_in[7];
    const float* b3    = (const float*)d_in[8];
    int E = in_sizes[1] / 2;

    k_init<<<IG, 256>>>(ei32, eattr, E);
    dim3 pg((BN + PB - 1)/PB, 2);
    k_proj<<<pg, PB>>>(x, W1, b1);
    long long items = 4LL * E;
    int blocks = (int)((items + BD - 1) / BD);
    k_edge<<<blocks, BD>>>(ei32, eattr, W1, W2, b2, E);
    k_out<<<pg, PB>>>((float*)d_out, W3, b3);
}

// round 15
// speedup vs baseline: 1.5079x; 1.2833x over previous
#include <cuda_runtime.h>

#define NB   4
#define NN   50000
#define FIN  32
#define H2   30
#define BN   (NB*NN)       // 200000 node-batch rows
#define BD   128           // edge-kernel block size
#define PB   256           // proj/out block size
#define IG   1024          // init grid

typedef unsigned long long ull;

// Static scratch (no allocations allowed).
__device__ __align__(128) float g_YA[(size_t)BN*32];   // x @ W1[0:32]
__device__ __align__(128) float g_YB[(size_t)BN*32];   // x @ W1[32:64] + b1
__device__ __align__(128) float g_SC[(size_t)BN*32];   // padded 30->32 accumulator
__device__ double g_sum, g_sumsq;
__device__ float  g_mean, g_istd;
__device__ int    g_is64;
__device__ unsigned g_ticket;

union F4U2 { float4 f4; ull u[2]; float f[4]; };
union F2U1 { float2 f2; ull u; float f[2]; };

__device__ __forceinline__ float sigmoidf(float x){          // final layer
    return __fdividef(1.0f, 1.0f + __expf(-x));
}
__device__ __forceinline__ float sigm_fast(float x){         // hidden layers
    float t;
    asm("tanh.approx.f32 %0, %1;" : "=f"(t) : "f"(x * 0.5f));
    return fmaf(t, 0.5f, 0.5f);
}
__device__ __forceinline__ ull pack2(float lo, float hi){
    ull r; asm("mov.b64 %0, {%1,%2};" : "=l"(r) : "f"(lo), "f"(hi)); return r;
}
#define FMA2(acc, a, b) asm("fma.rn.f32x2 %0, %1, %2, %0;" : "+l"(acc) : "l"(a), "l"(b))
#define ADD2(d, a, b)   asm("add.rn.f32x2 %0, %1, %2;"     : "=l"(d)  : "l"(a), "l"(b))

__device__ __forceinline__ void red_add_v4(float* p, float a, float b, float c, float d){
    asm volatile("red.global.add.v4.f32 [%0], {%1,%2,%3,%4};"
                 :: "l"(p), "f"(a), "f"(b), "f"(c), "f"(d) : "memory");
}

// ---------------- K0: zero SC + edge_attr stats + probe + finalize (fused) ----------------
__global__ void k_init(const int* __restrict__ ei32, const float* __restrict__ ea, int E){
    size_t n4 = (size_t)BN*32/4;
    float4 z = make_float4(0.f,0.f,0.f,0.f);
    float4* p = (float4*)g_SC;
    for (size_t i = (size_t)blockIdx.x*blockDim.x + threadIdx.x; i < n4;
         i += (size_t)gridDim.x*blockDim.x) p[i] = z;

    if (blockIdx.x==0 && threadIdx.x==0){
        int all_hi_zero = 1;
        for (int k = 1; k < 512; k += 2) all_hi_zero &= (ei32[k] == 0);
        g_is64 = all_hi_zero;
    }

    float s = 0.f, s2 = 0.f;
    for (int i = blockIdx.x*blockDim.x + threadIdx.x; i < E; i += gridDim.x*blockDim.x){
        float v = ea[i]; s += v; s2 = fmaf(v, v, s2);
    }
    #pragma unroll
    for (int o = 16; o; o >>= 1){
        s  += __shfl_down_sync(0xffffffffu, s,  o);
        s2 += __shfl_down_sync(0xffffffffu, s2, o);
    }
    __shared__ float ws[32], ws2[32];
    __shared__ int last;
    int lane = threadIdx.x & 31, w = threadIdx.x >> 5;
    if (lane == 0){ ws[w] = s; ws2[w] = s2; }
    __syncthreads();
    if (w == 0){
        int nw = blockDim.x >> 5;
        s  = (lane < nw) ? ws[lane]  : 0.f;
        s2 = (lane < nw) ? ws2[lane] : 0.f;
        #pragma unroll
        for (int o = 16; o; o >>= 1){
            s  += __shfl_down_sync(0xffffffffu, s,  o);
            s2 += __shfl_down_sync(0xffffffffu, s2, o);
        }
        if (lane == 0){ atomicAdd(&g_sum, (double)s); atomicAdd(&g_sumsq, (double)s2); }
    }
    if (threadIdx.x == 0){
        __threadfence();
        unsigned t = atomicAdd(&g_ticket, 1u);
        last = (t == (unsigned)(gridDim.x - 1));
    }
    __syncthreads();
    if (last && threadIdx.x == 0){
        double S = g_sum, S2 = g_sumsq;
        double mean = S / (double)E;
        double var  = (S2 - S*S/(double)E) / (double)(E - 1);
        g_mean = (float)mean;
        g_istd = (float)(1.0 / sqrt(var));
        g_ticket = 0u;
        g_sum = 0.0; g_sumsq = 0.0;
    }
}

// ---------------- KB: per-node projections, split halves, smem-staged I/O ----------------
__global__ __launch_bounds__(PB) void k_proj(
    const float* __restrict__ x, const float* __restrict__ W1,
    const float* __restrict__ b1)
{
    __shared__ float4 st[PB*9];
    __shared__ __align__(16) float sW[32*32];
    __shared__ __align__(16) float sb[32];
    int half = blockIdx.y;
    int tid = threadIdx.x;
    for (int k = tid; k < 32*32; k += PB) sW[k] = W1[half*32*32 + k];
    if (tid < 32) sb[tid] = half ? b1[tid] : 0.f;

    int base = blockIdx.x*PB;
    const float4* x4 = (const float4*)x;
    #pragma unroll
    for (int k = tid; k < PB*8; k += PB){
        int row = k >> 3, q = k & 7;
        int gr = base + row;
        if (gr < BN) st[row*9 + q] = x4[(size_t)gr*8 + q];
    }
    __syncthreads();

    F4U2 xr[8];
    #pragma unroll
    for (int q = 0; q < 8; q++) xr[q].f4 = st[tid*9 + q];

    __align__(16) ull acc[16];
    const float4* sb4 = (const float4*)sb;
    #pragma unroll
    for (int q = 0; q < 8; q++){
        F4U2 b; b.f4 = sb4[q];
        acc[2*q] = b.u[0]; acc[2*q+1] = b.u[1];
    }
    #pragma unroll
    for (int i = 0; i < 32; i++){
        float v = xr[i >> 2].f[i & 3];
        ull vv = pack2(v, v);
        const float4* wr = (const float4*)(sW + i*32);
        #pragma unroll
        for (int q = 0; q < 8; q++){
            F4U2 w; w.f4 = wr[q];
            FMA2(acc[2*q],   vv, w.u[0]);
            FMA2(acc[2*q+1], vv, w.u[1]);
        }
    }
    __syncthreads();
    const float4* aa = (const float4*)acc;
    #pragma unroll
    for (int q = 0; q < 8; q++) st[tid*9 + q] = aa[q];
    __syncthreads();
    float4* y4 = (float4*)(half ? g_YB : g_YA);
    #pragma unroll
    for (int k = tid; k < PB*8; k += PB){
        int row = k >> 3, q = k & 7;
        int gr = base + row;
        if (gr < BN) y4[(size_t)gr*8 + q] = st[row*9 + q];
    }
}

// ---------------- KD: edge MLP, 2 items/thread (same edge, b and b+2) ----------------
// Weight LDS amortized over 2 items; warp-local coalesced gather & scatter.
__global__ __launch_bounds__(BD) void k_edge(
    const int* __restrict__ ei32, const float* __restrict__ eattr,
    const float* __restrict__ W1, const float* __restrict__ W2,
    const float* __restrict__ b2, int E)
{
    __shared__ float4 sS[2*BD*9];               // 2 rows per thread, stride 9
    __shared__ __align__(16) float sW2[32*32];
    __shared__ __align__(16) float sw1c[32];
    __shared__ __align__(16) float sb2[32];

    int tid = threadIdx.x;
    int lane = tid & 31, w = tid >> 5;

    for (int k = tid; k < 32*32; k += BD){
        int i = k >> 5, j = k & 31;
        sW2[k] = (j < H2) ? W2[i*H2 + j] : 0.f;
    }
    if (tid < 32){
        sw1c[tid] = W1[64*32 + tid];
        sb2[tid]  = (tid < H2) ? b2[tid] : 0.f;
    }
    __syncthreads();                          // ONLY block barrier

    // Pair P handles items (e, b) and (e, b+2) where e = P>>1, b = P&1.
    long long P = (long long)blockIdx.x*BD + tid;
    bool active = P < 2LL*E;
    int e = active ? (int)(P >> 1) : 0;
    int b = (int)(P & 1);
    int is64 = g_is64;
    int src, tgt;
    if (is64){ src = ei32[2*(size_t)e]; tgt = ei32[2*((size_t)E + e)]; }
    else     { src = ei32[e];           tgt = ei32[E + e]; }
    float ea = active ? (eattr[e] - g_mean) * g_istd : 0.f;
    int ia = b*NN + src;                      // item A rows; item B = +2*NN
    int ib = b*NN + tgt;

    // Warp-local coalesced gather+add: 64 rows per warp (2 per thread).
    const float4* ya4 = (const float4*)g_YA;
    const float4* yb4 = (const float4*)g_YB;
    int rowbase = w*64;
    int q = lane & 7;
    int grp = lane >> 3;                      // 0..3
    #pragma unroll
    for (int it = 0; it < 16; it++){
        int rw = 4*it + grp;                  // row-in-warp 0..63
        int iaW = __shfl_sync(0xffffffffu, ia, rw >> 1) + (rw & 1)*2*NN;
        int ibW = __shfl_sync(0xffffffffu, ib, rw >> 1) + (rw & 1)*2*NN;
        int R = rowbase + rw;
        float4 va = ya4[(size_t)iaW*8 + q];
        float4 vb = yb4[(size_t)ibW*8 + q];
        float4 vs;
        vs.x = va.x + vb.x; vs.y = va.y + vb.y;
        vs.z = va.z + vb.z; vs.w = va.w + vb.w;
        sS[R*9 + q] = vs;
    }
    __syncwarp();

    // Interleaved layer1+layer2 for BOTH items; weights loaded once, used twice.
    __align__(16) ull accA[15], accB[15];
    const float4* sb24 = (const float4*)sb2;
    #pragma unroll
    for (int p = 0; p < 7; p++){
        F4U2 bb; bb.f4 = sb24[p];
        accA[2*p] = bb.u[0]; accA[2*p+1] = bb.u[1];
        accB[2*p] = bb.u[0]; accB[2*p+1] = bb.u[1];
    }
    { F2U1 bt; bt.f2 = *(const float2*)(sb2 + 28); accA[14] = bt.u; accB[14] = bt.u; }

    int RA = rowbase + 2*lane;                // my item A row
    ull eaea = pack2(ea, ea);
    const float4* w1c4 = (const float4*)sw1c;
    #pragma unroll
    for (int p = 0; p < 8; p++){
        F4U2 aA; aA.f4 = sS[RA*9 + p];
        F4U2 aB; aB.f4 = sS[(RA + 1)*9 + p];
        F4U2 wv; wv.f4 = w1c4[p];
        ull sA0 = aA.u[0], sA1 = aA.u[1];
        ull sB0 = aB.u[0], sB1 = aB.u[1];
        FMA2(sA0, eaea, wv.u[0]); FMA2(sA1, eaea, wv.u[1]);
        FMA2(sB0, eaea, wv.u[0]); FMA2(sB1, eaea, wv.u[1]);
        F4U2 rA; rA.u[0] = sA0; rA.u[1] = sA1;
        F4U2 rB; rB.u[0] = sB0; rB.u[1] = sB1;
        #pragma unroll
        for (int c = 0; c < 4; c++){
            float hA = sigm_fast(rA.f[c]);
            float hB = sigm_fast(rB.f[c]);
            ull hhA = pack2(hA, hA);
            ull hhB = pack2(hB, hB);
            const float4* wr = (const float4*)(sW2 + (4*p + c)*32);
            #pragma unroll
            for (int m = 0; m < 7; m++){
                F4U2 w2v; w2v.f4 = wr[m];
                FMA2(accA[2*m],   hhA, w2v.u[0]);
                FMA2(accA[2*m+1], hhA, w2v.u[1]);
                FMA2(accB[2*m],   hhB, w2v.u[0]);
                FMA2(accB[2*m+1], hhB, w2v.u[1]);
            }
            F2U1 wt; wt.f2 = *(const float2*)(sW2 + (4*p + c)*32 + 28);
            FMA2(accA[14], hhA, wt.u);
            FMA2(accB[14], hhB, wt.u);
        }
    }

    // In-place sigmoid, masked, staged into own rows (36-float stride, padded).
    float msk = active ? 1.f : 0.f;
    {
        float* mrA = (float*)sS + RA*36;
        float* mrB = (float*)sS + (RA + 1)*36;
        const float* avA = (const float*)accA;
        const float* avB = (const float*)accB;
        #pragma unroll
        for (int p = 0; p < 7; p++){
            float4 vA, vB;
            vA.x = sigm_fast(avA[4*p+0]) * msk;
            vA.y = sigm_fast(avA[4*p+1]) * msk;
            vA.z = sigm_fast(avA[4*p+2]) * msk;
            vA.w = sigm_fast(avA[4*p+3]) * msk;
            vB.x = sigm_fast(avB[4*p+0]) * msk;
            vB.y = sigm_fast(avB[4*p+1]) * msk;
            vB.z = sigm_fast(avB[4*p+2]) * msk;
            vB.w = sigm_fast(avB[4*p+3]) * msk;
            *(float4*)(mrA + 4*p) = vA;
            *(float4*)(mrB + 4*p) = vB;
        }
        float4 tA, tB;
        tA.x = sigm_fast(avA[28]) * msk; tA.y = sigm_fast(avA[29]) * msk;
        tA.z = 0.f; tA.w = 0.f;
        tB.x = sigm_fast(avB[28]) * msk; tB.y = sigm_fast(avB[29]) * msk;
        tB.z = 0.f; tB.w = 0.f;
        *(float4*)(mrA + 28) = tA;
        *(float4*)(mrB + 28) = tB;
    }
    __syncwarp();

    // Warp-local coalesced scatter: 8 lanes per row, full 128B-line red.v4.
    float* sH = (float*)sS;
    #pragma unroll
    for (int it = 0; it < 16; it++){
        int rw = 4*it + grp;
        int iaW = __shfl_sync(0xffffffffu, ia, rw >> 1) + (rw & 1)*2*NN;
        int ibW = __shfl_sync(0xffffffffu, ib, rw >> 1) + (rw & 1)*2*NN;
        int R = rowbase + rw;
        float4 v = *(const float4*)(sH + R*36 + 4*q);
        red_add_v4(g_SC + (size_t)ibW*32 + 4*q,  v.x,  v.y,  v.z,  v.w);
        red_add_v4(g_SC + (size_t)iaW*32 + 4*q, -v.x, -v.y, -v.z, -v.w);
    }
}

// ---------------- KE: out = sigmoid(SC @ W3 + b3), split 16-col halves, staged I/O ----------------
__global__ __launch_bounds__(PB) void k_out(
    float* __restrict__ out, const float* __restrict__ W3,
    const float* __restrict__ b3)
{
    __shared__ float4 st[PB*9];
    __shared__ __align__(16) float sW[30*16];
    __shared__ __align__(16) float sb[16];
    int half = blockIdx.y;
    int tid = threadIdx.x;
    for (int k = tid; k < 30*16; k += PB){
        int r = k >> 4, c = k & 15;
        sW[k] = W3[r*32 + half*16 + c];
    }
    if (tid < 16) sb[tid] = b3[half*16 + tid];

    int base = blockIdx.x*PB;
    const float4* sc4 = (const float4*)g_SC;
    #pragma unroll
    for (int k = tid; k < PB*8; k += PB){
        int row = k >> 3, q = k & 7;
        int gr = base + row;
        if (gr < BN) st[row*9 + q] = sc4[(size_t)gr*8 + q];
    }
    __syncthreads();

    F4U2 sr[8];
    #pragma unroll
    for (int q = 0; q < 8; q++) sr[q].f4 = st[tid*9 + q];

    __align__(16) ull acc[8];
    const float4* sb4 = (const float4*)sb;
    #pragma unroll
    for (int q = 0; q < 4; q++){
        F4U2 bb; bb.f4 = sb4[q];
        acc[2*q] = bb.u[0]; acc[2*q+1] = bb.u[1];
    }
    #pragma unroll
    for (int k = 0; k < 30; k++){
        float sv = sr[k >> 2].f[k & 3];
        ull vv = pack2(sv, sv);
        const float4* wr = (const float4*)(sW + k*16);
        #pragma unroll
        for (int q = 0; q < 4; q++){
            F4U2 w; w.f4 = wr[q];
            FMA2(acc[2*q],   vv, w.u[0]);
            FMA2(acc[2*q+1], vv, w.u[1]);
        }
    }
    __align__(16) float res[16];
    #pragma unroll
    for (int q = 0; q < 4; q++){
        F4U2 r; r.u[0] = acc[2*q]; r.u[1] = acc[2*q+1];
        res[4*q+0] = sigmoidf(r.f[0]);
        res[4*q+1] = sigmoidf(r.f[1]);
        res[4*q+2] = sigmoidf(r.f[2]);
        res[4*q+3] = sigmoidf(r.f[3]);
    }

    __syncthreads();
    float4* st5 = (float4*)st;
    const float4* rr = (const float4*)res;
    #pragma unroll
    for (int q = 0; q < 4; q++) st5[tid*5 + q] = rr[q];
    __syncthreads();
    float4* o4 = (float4*)out;
    #pragma unroll
    for (int k = tid; k < PB*4; k += PB){
        int row = k >> 2, q = k & 3;
        int gr = base + row;
        if (gr < BN) o4[(size_t)gr*8 + half*4 + q] = st5[row*5 + q];
    }
}

extern "C" void kernel_launch(void* const* d_in, const int* in_sizes, int n_in,
                              void* d_out, int out_size){
    const float* x     = (const float*)d_in[0];
    const int*   ei32  = (const int*)d_in[1];
    const float* eattr = (const float*)d_in[2];
    const float* W1    = (const float*)d_in[3];
    const float* b1    = (const float*)d_in[4];
    const float* W2    = (const float*)d_in[5];
    const float* b2    = (const float*)d_in[6];
    const float* W3    = (const float*)d_in[7];
    const float* b3    = (const float*)d_in[8];
    int E = in_sizes[1] / 2;

    k_init<<<IG, 256>>>(ei32, eattr, E);
    dim3 pg((BN + PB - 1)/PB, 2);
    k_proj<<<pg, PB>>>(x, W1, b1);
    long long pairs = 2LL * E;
    int blocks = (int)((pairs + BD - 1) / BD);
    k_edge<<<blocks, BD>>>(ei32, eattr, W1, W2, b2, E);
    k_out<<<pg, PB>>>((float*)d_out, W3, b3);
}